// round 16
// baseline (speedup 1.0000x reference)
#include <cuda_runtime.h>
#include <cooperative_groups.h>
namespace cg = cooperative_groups;

#define SEQ    4096
#define BATCH  16
#define HIDDEN 512
#define SPC    16                    // s per chunk
#define CPB    (SEQ / SPC)           // 256 chunks per batch
#define SLOTS  46                    // persistent slots per batch (736 blocks = 5/SM max-resident)
#define NBLK   (BATCH * SLOTS)       // 736
#define CTXN   (BATCH * HIDDEN)      // 8192

// Scratch (no allocations allowed) — all fully re-written every launch.
__device__ float g_dec[BATCH * HIDDEN];              // decoder features [b][h]
__device__ float g_w[BATCH * SEQ];                   // unnormalized masked weights
__device__ float g_zpart[BATCH * SLOTS];             // per-(b,slot) Z partials
__device__ float g_part[BATCH * SLOTS * HIDDEN];     // ctx partials [b][slot][h]

__device__ __forceinline__ float tanh_fast(float x) {
    float y;
    asm("tanh.approx.f32 %0, %1;" : "=f"(y) : "f"(x));
    return y;
}

// ---------------------------------------------------------------------------
// KALL: cooperative single kernel.
//   Phase 0: dec[b,k] = dot(x[b], W[k]) + bias[k]   (warp-per-output)
//   grid.sync()
//   Phase 1: champion kmain body (scores + context partials)
//   grid.sync()
//   Phase 2: epilogue (ctx reduce + attention normalize)
// Grid 736 x 256, __launch_bounds__(256,5) -> fully co-resident.
// ---------------------------------------------------------------------------
__global__ void __launch_bounds__(256, 5)
kall(const float* __restrict__ x,    const float* __restrict__ W,
     const float* __restrict__ bias, const float* __restrict__ encf,
     const float* __restrict__ enc,  const float* __restrict__ mask,
     const float* __restrict__ tss,  const float* __restrict__ v,
     float* __restrict__ out) {
    cg::grid_group grid = cg::this_grid();

    int bid  = blockIdx.x;
    int b    = bid / SLOTS;
    int slot = bid % SLOTS;
    int tid  = threadIdx.x;               // 256
    int warp = tid >> 5, lane = tid & 31;

    float* out_newsum = out + CTXN + BATCH * SEQ;

    __shared__ float4 ds_s[HIDDEN / 4];   // 128 float4
    __shared__ float4 vs_s[HIDDEN / 4];
    __shared__ float4 red_s[HIDDEN / 4];  // parity-reduce staging
    __shared__ float  ws[SPC];
    __shared__ float  zs[8];

    // ================= Phase 0: decoder features =================
    {
        int wg = bid * 8 + warp;          // 0..5887
#pragma unroll
        for (int pass = 0; pass < 2; ++pass) {
            int o = wg + pass * NBLK * 8; // 0..11775; valid < 8192
            if (o < CTXN) {
                int ob = o >> 9;          // batch
                int k  = o & (HIDDEN - 1);
                const float4* xr = reinterpret_cast<const float4*>(x + (size_t)ob * HIDDEN);
                const float4* Wr = reinterpret_cast<const float4*>(W + (size_t)k * HIDDEN);
                float acc = 0.0f;
#pragma unroll
                for (int j = 0; j < 4; ++j) {
                    float4 wv = Wr[lane + j * 32];
                    float4 xv = __ldg(&xr[lane + j * 32]);
                    acc += wv.x * xv.x + wv.y * xv.y + wv.z * xv.z + wv.w * xv.w;
                }
#pragma unroll
                for (int off = 16; off; off >>= 1)
                    acc += __shfl_down_sync(0xffffffffu, acc, off);
                if (lane == 0) g_dec[o] = acc + bias[k];
            }
        }
    }

    grid.sync();

    // ================= Phase 1: champion kmain body =================
    // Stage decoder features + v into shared (once per block).
    if (tid < 128) ds_s[tid] = reinterpret_cast<const float4*>(g_dec + b * HIDDEN)[tid];
    else           vs_s[tid - 128] = reinterpret_cast<const float4*>(v)[tid - 128];
    __syncthreads();

    int par = tid >> 7;                   // 0/1
    int h4  = tid & 127;
    const size_t strideS = (size_t)BATCH * (HIDDEN / 4);     // float4s per s-step
    const float4* enc4 = reinterpret_cast<const float4*>(enc);
    float4 ctx = make_float4(0.f, 0.f, 0.f, 0.f);
    float zacc = 0.0f;

    for (int c = slot; c < CPB; c += SLOTS) {
        int sbase = c * SPC;
        int s0 = sbase + warp * 2;

        // ---- Phase A: 2 rows per warp ----
        float4 ev[2][4];
#pragma unroll
        for (int i = 0; i < 2; ++i) {
            const float4* row =
                reinterpret_cast<const float4*>(encf + ((size_t)(s0 + i) * BATCH + b) * HIDDEN);
#pragma unroll
            for (int j = 0; j < 4; ++j) ev[i][j] = row[lane + j * 32];
        }
        float acc[2] = {0.f, 0.f};
#pragma unroll
        for (int j = 0; j < 4; ++j) {
            float4 d4 = ds_s[lane + j * 32];     // LDS.128, conflict-free
            float4 v4 = vs_s[lane + j * 32];
#pragma unroll
            for (int i = 0; i < 2; ++i) {
                acc[i] += tanh_fast(d4.x + ev[i][j].x) * v4.x;
                acc[i] += tanh_fast(d4.y + ev[i][j].y) * v4.y;
                acc[i] += tanh_fast(d4.z + ev[i][j].z) * v4.z;
                acc[i] += tanh_fast(d4.w + ev[i][j].w) * v4.w;
            }
        }
#pragma unroll
        for (int i = 0; i < 2; ++i) {
#pragma unroll
            for (int off = 16; off; off >>= 1)
                acc[i] += __shfl_down_sync(0xffffffffu, acc[i], off);
            if (lane == 0) {
                int s = s0 + i;
                float e = expf(acc[i]);
                float t = tss[b * SEQ + s];
                float w = mask[b * SEQ + s] * e / t;
                out_newsum[b * SEQ + s] = e + t;
                g_w[b * SEQ + s] = w;
                ws[warp * 2 + i] = w;
                zacc += w;
            }
        }
        __syncthreads();

        // ---- Phase B: accumulate ctx for this chunk ----
        const float4* p = enc4 + ((size_t)(sbase + par) * BATCH + b) * (HIDDEN / 4) + h4;
#pragma unroll
        for (int i = 0; i < SPC / 2; ++i) {
            float  wv = ws[2 * i + par];
            float4 e  = __ldg(p + (size_t)(2 * i) * strideS);
            ctx.x += wv * e.x; ctx.y += wv * e.y; ctx.z += wv * e.z; ctx.w += wv * e.w;
        }
        __syncthreads();   // keep warps phase-aligned (proven necessary in R9)
    }

    // ---- Parity reduce: one ctx partial per (b,slot,h) ----
    if (par == 1) red_s[h4] = ctx;
    __syncthreads();
    if (par == 0) {
        float4 o = red_s[h4];
        ctx.x += o.x; ctx.y += o.y; ctx.z += o.z; ctx.w += o.w;
        reinterpret_cast<float4*>(g_part)
            [((size_t)b * SLOTS + slot) * (HIDDEN / 4) + h4] = ctx;
    }

    // Deterministic Z partial for this (b, slot).
    if (lane == 0) zs[warp] = zacc;
    __syncthreads();
    if (tid == 0) {
        float z = 0.0f;
#pragma unroll
        for (int i = 0; i < 8; ++i) z += zs[i];
        g_zpart[b * SLOTS + slot] = z;
    }

    grid.sync();

    // ================= Phase 2: epilogue =================
    {
        int gt = bid * 256 + tid;                 // 0..188415
        if (gt < CTXN) {
            int eb = gt >> 9;
            float Z = 0.0f;
#pragma unroll
            for (int j = 0; j < SLOTS; ++j) Z += g_zpart[eb * SLOTS + j];
            float acc = 0.0f;
            int h = gt & (HIDDEN - 1);
#pragma unroll
            for (int p = 0; p < SLOTS; ++p)
                acc += g_part[((size_t)eb * SLOTS + p) * HIDDEN + h];
            out[gt] = acc / Z;
        } else if (gt < CTXN + BATCH * SEQ) {
            int i  = gt - CTXN;                   // 0..65535
            int eb = i >> 12;
            float Z = 0.0f;
#pragma unroll
            for (int j = 0; j < SLOTS; ++j) Z += g_zpart[eb * SLOTS + j];
            out[CTXN + i] = g_w[i] / Z;
        }
    }
}

// ---------------------------------------------------------------------------
extern "C" void kernel_launch(void* const* d_in, const int* in_sizes, int n_in,
                              void* d_out, int out_size) {
    const float* x    = (const float*)d_in[0];  // outputs_hidden [1,16,512]
    const float* enc  = (const float*)d_in[1];  // encoder_out [4096,16,512]
    const float* encf = (const float*)d_in[2];  // encoder_features [4096,16,512]
    const float* mask = (const float*)d_in[3];  // encoder_mask [16,1,4096]
    const float* tss  = (const float*)d_in[4];  // temporal_scores_sum [16,1,4096]
    const float* W    = (const float*)d_in[5];  // W_feat [512,512]
    const float* bias = (const float*)d_in[6];  // b_feat [512]
    const float* v    = (const float*)d_in[7];  // v_attn [512]

    float* out = (float*)d_out;

    void* args[] = {
        (void*)&x, (void*)&W, (void*)&bias, (void*)&encf, (void*)&enc,
        (void*)&mask, (void*)&tss, (void*)&v, (void*)&out
    };
    cudaLaunchCooperativeKernel((void*)kall, dim3(NBLK, 1, 1), dim3(256, 1, 1),
                                args, 0, (cudaStream_t)0);
}

// round 17
// speedup vs baseline: 1.0326x; 1.0326x over previous
#include <cuda_runtime.h>

#define SEQ    4096
#define BATCH  16
#define HIDDEN 512
#define SPC    16                    // s per chunk
#define CPB    (SEQ / SPC)           // 256 chunks per batch
#define SLOTS  46                    // persistent slots per batch (736 blocks = 5/SM)
#define CTXN   (BATCH * HIDDEN)      // 8192

// Scratch (no allocations allowed) — all fully re-written every launch.
__device__ float g_dec[BATCH * HIDDEN];              // decoder features [b][h]
__device__ float g_w[BATCH * SEQ];                   // unnormalized masked weights
__device__ float g_zpart[BATCH * SLOTS];             // per-(b,slot) Z partials
__device__ float g_part[BATCH * SLOTS * HIDDEN];     // ctx partials [b][slot][h]

__device__ __forceinline__ float tanh_fast(float x) {
    float y;
    asm("tanh.approx.f32 %0, %1;" : "=f"(y) : "f"(x));
    return y;
}

// ---------------------------------------------------------------------------
// K0: decoder_features[b,k] = dot(x[b,:], W[k,:]) + bias[k].
// Grid 2048 = 16 b * 128 row-groups of 4. Block 256 (8 warps):
// TWO warps per output row, each resolving a 1KB half-row (2 float4/thread),
// combined via smem. Halves the per-output latency chain vs 1-warp-per-row.
// ---------------------------------------------------------------------------
__global__ void k0_dec(const float* __restrict__ x, const float* __restrict__ W,
                       const float* __restrict__ bias) {
    int b    = blockIdx.x >> 7;          // 128 row-groups per batch
    int rg   = blockIdx.x & 127;
    int tid  = threadIdx.x;              // 256
    int warp = tid >> 5, lane = tid & 31;
    int row  = rg * 4 + (warp >> 1);     // 4 rows per block
    int half = warp & 1;                 // which 256-element half of the dot

    __shared__ float sm[8];

    const float4* Wr = reinterpret_cast<const float4*>(W + (size_t)row * HIDDEN) + half * 64;
    const float4* xr = reinterpret_cast<const float4*>(x + (size_t)b * HIDDEN) + half * 64;

    float4 wv0 = Wr[lane], wv1 = Wr[lane + 32];
    float4 xv0 = __ldg(&xr[lane]), xv1 = __ldg(&xr[lane + 32]);

    float acc = wv0.x * xv0.x + wv0.y * xv0.y + wv0.z * xv0.z + wv0.w * xv0.w
              + wv1.x * xv1.x + wv1.y * xv1.y + wv1.z * xv1.z + wv1.w * xv1.w;
#pragma unroll
    for (int off = 16; off; off >>= 1) acc += __shfl_down_sync(0xffffffffu, acc, off);
    if (lane == 0) sm[warp] = acc;
    __syncthreads();

    if (tid < 4) {
        int r = rg * 4 + tid;
        g_dec[b * HIDDEN + r] = sm[2 * tid] + sm[2 * tid + 1] + bias[r];
    }
}

// ---------------------------------------------------------------------------
// KMAIN: persistent fused scores+context — champion body (R11/R15), SLOTS=46.
// Grid 736 = 16 b * 46 slots, block 256 (8 warps).
// ---------------------------------------------------------------------------
__global__ void __launch_bounds__(256, 5)
kmain(const float* __restrict__ encf, const float* __restrict__ enc,
      const float* __restrict__ mask, const float* __restrict__ tss,
      const float* __restrict__ v,    float* __restrict__ out_newsum) {
    int b    = blockIdx.x / SLOTS;
    int slot = blockIdx.x % SLOTS;
    int tid  = threadIdx.x;               // 256
    int warp = tid >> 5, lane = tid & 31;

    __shared__ float4 ds_s[HIDDEN / 4];   // 128 float4
    __shared__ float4 vs_s[HIDDEN / 4];
    __shared__ float4 red_s[HIDDEN / 4];  // parity-reduce staging
    __shared__ float  ws[SPC];
    __shared__ float  zs[8];

    // Stage decoder features + v into shared (once per block).
    if (tid < 128) ds_s[tid] = reinterpret_cast<const float4*>(g_dec + b * HIDDEN)[tid];
    else           vs_s[tid - 128] = reinterpret_cast<const float4*>(v)[tid - 128];
    __syncthreads();

    // Phase-B persistent state.
    int par = tid >> 7;                   // 0/1
    int h4  = tid & 127;
    const size_t strideS = (size_t)BATCH * (HIDDEN / 4);     // float4s per s-step
    const float4* enc4 = reinterpret_cast<const float4*>(enc);
    float4 ctx = make_float4(0.f, 0.f, 0.f, 0.f);
    float zacc = 0.0f;

    for (int c = slot; c < CPB; c += SLOTS) {
        int sbase = c * SPC;
        int s0 = sbase + warp * 2;

        // ---- Phase A: 2 rows per warp ----
        float4 ev[2][4];
#pragma unroll
        for (int i = 0; i < 2; ++i) {
            const float4* row =
                reinterpret_cast<const float4*>(encf + ((size_t)(s0 + i) * BATCH + b) * HIDDEN);
#pragma unroll
            for (int j = 0; j < 4; ++j) ev[i][j] = row[lane + j * 32];
        }
        float acc[2] = {0.f, 0.f};
#pragma unroll
        for (int j = 0; j < 4; ++j) {
            float4 d4 = ds_s[lane + j * 32];     // LDS.128, conflict-free
            float4 v4 = vs_s[lane + j * 32];
#pragma unroll
            for (int i = 0; i < 2; ++i) {
                acc[i] += tanh_fast(d4.x + ev[i][j].x) * v4.x;
                acc[i] += tanh_fast(d4.y + ev[i][j].y) * v4.y;
                acc[i] += tanh_fast(d4.z + ev[i][j].z) * v4.z;
                acc[i] += tanh_fast(d4.w + ev[i][j].w) * v4.w;
            }
        }
#pragma unroll
        for (int i = 0; i < 2; ++i) {
#pragma unroll
            for (int off = 16; off; off >>= 1)
                acc[i] += __shfl_down_sync(0xffffffffu, acc[i], off);
            if (lane == 0) {
                int s = s0 + i;
                float e = expf(acc[i]);
                float t = tss[b * SEQ + s];
                float w = mask[b * SEQ + s] * e / t;
                out_newsum[b * SEQ + s] = e + t;
                g_w[b * SEQ + s] = w;
                ws[warp * 2 + i] = w;
                zacc += w;
            }
        }
        __syncthreads();

        // ---- Phase B: accumulate ctx for this chunk ----
        const float4* p = enc4 + ((size_t)(sbase + par) * BATCH + b) * (HIDDEN / 4) + h4;
#pragma unroll
        for (int i = 0; i < SPC / 2; ++i) {
            float  wv = ws[2 * i + par];
            float4 e  = __ldg(p + (size_t)(2 * i) * strideS);
            ctx.x += wv * e.x; ctx.y += wv * e.y; ctx.z += wv * e.z; ctx.w += wv * e.w;
        }
        __syncthreads();   // keep warps phase-aligned (proven necessary in R9)
    }

    // ---- Parity reduce: one ctx partial per (b,slot,h) ----
    if (par == 1) red_s[h4] = ctx;
    __syncthreads();
    if (par == 0) {
        float4 o = red_s[h4];
        ctx.x += o.x; ctx.y += o.y; ctx.z += o.z; ctx.w += o.w;
        reinterpret_cast<float4*>(g_part)
            [((size_t)b * SLOTS + slot) * (HIDDEN / 4) + h4] = ctx;
    }

    // Deterministic Z partial for this (b, slot).
    if (lane == 0) zs[warp] = zacc;
    __syncthreads();
    if (tid == 0) {
        float z = 0.0f;
#pragma unroll
        for (int i = 0; i < 8; ++i) z += zs[i];
        g_zpart[b * SLOTS + slot] = z;
    }
}

// ---------------------------------------------------------------------------
// K4 (fused epilogue): blocks 0..31: ctx = (sum of 46 partials)/Z -> out[0:8192)
//                      blocks 32..287: attention = w/Z -> out[8192:73728)
// ---------------------------------------------------------------------------
__global__ void k4_final(float* __restrict__ out) {
    int bid = blockIdx.x, tid = threadIdx.x;
    if (bid < 32) {
        int i = bid * 256 + tid;            // 0..8191
        int b = i >> 9;
        float Z = 0.0f;
#pragma unroll
        for (int j = 0; j < SLOTS; ++j) Z += g_zpart[b * SLOTS + j];
        float acc = 0.0f;
        int h = i & (HIDDEN - 1);
#pragma unroll
        for (int p = 0; p < SLOTS; ++p)
            acc += g_part[((size_t)b * SLOTS + p) * HIDDEN + h];
        out[i] = acc / Z;
    } else {
        int i = (bid - 32) * 256 + tid;     // 0..65535
        int b = i >> 12;
        float Z = 0.0f;
#pragma unroll
        for (int j = 0; j < SLOTS; ++j) Z += g_zpart[b * SLOTS + j];
        out[CTXN + i] = g_w[i] / Z;
    }
}

// ---------------------------------------------------------------------------
extern "C" void kernel_launch(void* const* d_in, const int* in_sizes, int n_in,
                              void* d_out, int out_size) {
    const float* x    = (const float*)d_in[0];  // outputs_hidden [1,16,512]
    const float* enc  = (const float*)d_in[1];  // encoder_out [4096,16,512]
    const float* encf = (const float*)d_in[2];  // encoder_features [4096,16,512]
    const float* mask = (const float*)d_in[3];  // encoder_mask [16,1,4096]
    const float* tss  = (const float*)d_in[4];  // temporal_scores_sum [16,1,4096]
    const float* W    = (const float*)d_in[5];  // W_feat [512,512]
    const float* bias = (const float*)d_in[6];  // b_feat [512]
    const float* v    = (const float*)d_in[7];  // v_attn [512]

    float* out        = (float*)d_out;
    float* out_newsum = out + CTXN + BATCH * SEQ;  // third output

    k0_dec  <<<2048,          256>>>(x, W, bias);
    kmain   <<<BATCH * SLOTS, 256>>>(encf, enc, mask, tss, v, out_newsum);
    k4_final<<<288,           256>>>(out);
}